// round 4
// baseline (speedup 1.0000x reference)
#include <cuda_runtime.h>

// ============================================================================
// Fully-fused Mix9sNet: one CTA per (direction, batch) pair.
// Whole [128 x 225] activation plane resident in SMEM (double buffered).
// fp32 math via packed fma.rn.f32x2. Thread tile: 4 pixels x 16 channels
// (8 FMA2 per activation LDS).
// ============================================================================

typedef unsigned long long ULL;

#define CM    128
#define CO    64
#define NPIX  225
#define STR   226           // channel stride in smem; slot 225 is a zero sentinel
#define NTHR  512
#define SMEM_BYTES (2 * CM * STR * 4)   // 231424 bytes

// -------- pre-transposed weight scratch ([tap][c][o] / [c][o] layouts) ------
__device__ __align__(16) float g_w0 [3 * 2 * 128];
__device__ __align__(16) float g_dw [4][3 * 128 * 128];
__device__ __align__(16) float g_pw [4][128 * 128];
__device__ __align__(16) float g_c01[128 * 128];
__device__ __align__(16) float g_c02[128 * 128];
__device__ __align__(16) float g_fin[128 * 64];

// ------------------------------ f32x2 helpers -------------------------------
__device__ __forceinline__ ULL pack2(float lo, float hi) {
    ULL r; asm("mov.b64 %0, {%1, %2};" : "=l"(r) : "f"(lo), "f"(hi)); return r;
}
__device__ __forceinline__ float2 unpack2(ULL v) {
    float2 f; asm("mov.b64 {%0, %1}, %2;" : "=f"(f.x), "=f"(f.y) : "l"(v)); return f;
}
__device__ __forceinline__ void fma2(ULL& d, ULL a, ULL b) {
    asm("fma.rn.f32x2 %0, %1, %2, %0;" : "+l"(d) : "l"(a), "l"(b));
}
__device__ __forceinline__ float silu_f(float x) {
    return __fdividef(x, 1.0f + __expf(-x));
}

// ------------------------------ weight prep ---------------------------------
__global__ void prep_kernel(const float* __restrict__ w0,
                            const float* __restrict__ dw,
                            const float* __restrict__ pw,
                            const float* __restrict__ w1,
                            const float* __restrict__ w2,
                            const float* __restrict__ wf)
{
    int t  = blockIdx.x * blockDim.x + threadIdx.x;
    int nt = gridDim.x * blockDim.x;
    for (int i = t; i < 3 * 2 * 128; i += nt) {
        int tap = i / 256, c = (i >> 7) & 1, o = i & 127;
        g_w0[i] = w0[(o * 2 + c) * 3 + tap];
    }
    for (int i = t; i < 4 * 3 * 128 * 128; i += nt) {
        int l = i / (3 * 128 * 128);
        int r = i % (3 * 128 * 128);
        int tap = r / (128 * 128);
        int c = (r >> 7) & 127;
        int o = r & 127;
        g_dw[l][r] = dw[(((l * 128 + o) * 128 + c) * 3) + tap];
    }
    for (int i = t; i < 4 * 128 * 128; i += nt) {
        int l = i / 16384, r = i % 16384;
        int c = r >> 7, o = r & 127;
        g_pw[l][r] = pw[(l * 128 + o) * 128 + c];
    }
    for (int i = t; i < 128 * 128; i += nt) {
        int c = i >> 7, o = i & 127;
        g_c01[i] = w1[o * 128 + c];
        g_c02[i] = w2[o * 128 + c];
    }
    for (int i = t; i < 128 * 64; i += nt) {
        int c = i / 64, o = i % 64;
        g_fin[i] = wf[o * 128 + c];
    }
}

// ------------------------------ conv phases ---------------------------------
// Thread tile: 4 pixels (offC[0..3]) x 16 output channels (o0..o0+15).
// TAPS: 3-tap directional conv; RES: dst += silu(conv), else dst = silu(conv).
template<int CIN, bool TAPS, bool RES>
__device__ __forceinline__ void conv_phase(
    const float* __restrict__ src, float* __restrict__ dst,
    const float* __restrict__ Wt, const float* __restrict__ bias,
    int o0, const int* __restrict__ offC,
    const int* __restrict__ off0, const int* __restrict__ off2)
{
    ULL acc[4][8];
    {
        const ulonglong2* bv = reinterpret_cast<const ulonglong2*>(bias + o0);
        ulonglong2 t0 = bv[0], t1 = bv[1], t2 = bv[2], t3 = bv[3];
        ULL b[8] = {t0.x, t0.y, t1.x, t1.y, t2.x, t2.y, t3.x, t3.y};
        #pragma unroll
        for (int k = 0; k < 4; ++k)
            #pragma unroll
            for (int g = 0; g < 8; ++g) acc[k][g] = b[g];
    }

    #pragma unroll 2
    for (int c = 0; c < CIN; ++c) {
        const float* Sc = src + c * STR;
        {   // center tap
            const ulonglong2* wv = reinterpret_cast<const ulonglong2*>(
                Wt + ((TAPS ? CIN : 0) + c) * 128 + o0);
            ulonglong2 a = wv[0], b2 = wv[1], c2 = wv[2], d2 = wv[3];
            ULL w[8] = {a.x, a.y, b2.x, b2.y, c2.x, c2.y, d2.x, d2.y};
            #pragma unroll
            for (int k = 0; k < 4; ++k) {
                float v = Sc[offC[k]];
                ULL dv = pack2(v, v);
                #pragma unroll
                for (int g = 0; g < 8; ++g) fma2(acc[k][g], dv, w[g]);
            }
        }
        if (TAPS) {
            {   // tap 0
                const ulonglong2* wv = reinterpret_cast<const ulonglong2*>(
                    Wt + c * 128 + o0);
                ulonglong2 a = wv[0], b2 = wv[1], c2 = wv[2], d2 = wv[3];
                ULL w[8] = {a.x, a.y, b2.x, b2.y, c2.x, c2.y, d2.x, d2.y};
                #pragma unroll
                for (int k = 0; k < 4; ++k) {
                    float v = Sc[off0[k]];
                    ULL dv = pack2(v, v);
                    #pragma unroll
                    for (int g = 0; g < 8; ++g) fma2(acc[k][g], dv, w[g]);
                }
            }
            {   // tap 2
                const ulonglong2* wv = reinterpret_cast<const ulonglong2*>(
                    Wt + (2 * CIN + c) * 128 + o0);
                ulonglong2 a = wv[0], b2 = wv[1], c2 = wv[2], d2 = wv[3];
                ULL w[8] = {a.x, a.y, b2.x, b2.y, c2.x, c2.y, d2.x, d2.y};
                #pragma unroll
                for (int k = 0; k < 4; ++k) {
                    float v = Sc[off2[k]];
                    ULL dv = pack2(v, v);
                    #pragma unroll
                    for (int g = 0; g < 8; ++g) fma2(acc[k][g], dv, w[g]);
                }
            }
        }
    }

    #pragma unroll
    for (int k = 0; k < 4; ++k) {
        int p = offC[k];
        if (p < NPIX) {
            #pragma unroll
            for (int g = 0; g < 8; ++g) {
                float2 f = unpack2(acc[k][g]);
                float lo = silu_f(f.x), hi = silu_f(f.y);
                float* dp = dst + (o0 + 2 * g) * STR + p;
                if (RES) { dp[0] += lo; dp[STR] += hi; }
                else     { dp[0]  = lo; dp[STR]  = hi; }
            }
        }
    }
}

// final 1x1 conv (no activation): 4 px x 8 channels per thread, write global.
__device__ __forceinline__ void final_phase(
    const float* __restrict__ src, float* __restrict__ dst,
    const float* __restrict__ Wt, const float* __restrict__ bias,
    int o0, const int* __restrict__ offC)
{
    ULL acc[4][4];
    {
        const ulonglong2* bv = reinterpret_cast<const ulonglong2*>(bias + o0);
        ulonglong2 t0 = bv[0], t1 = bv[1];
        ULL b[4] = {t0.x, t0.y, t1.x, t1.y};
        #pragma unroll
        for (int k = 0; k < 4; ++k)
            #pragma unroll
            for (int g = 0; g < 4; ++g) acc[k][g] = b[g];
    }
    #pragma unroll 4
    for (int c = 0; c < CM; ++c) {
        const float* Sc = src + c * STR;
        const ulonglong2* wv = reinterpret_cast<const ulonglong2*>(Wt + c * CO + o0);
        ulonglong2 a = wv[0], b2 = wv[1];
        ULL w[4] = {a.x, a.y, b2.x, b2.y};
        #pragma unroll
        for (int k = 0; k < 4; ++k) {
            float v = Sc[offC[k]];
            ULL dv = pack2(v, v);
            #pragma unroll
            for (int g = 0; g < 4; ++g) fma2(acc[k][g], dv, w[g]);
        }
    }
    #pragma unroll
    for (int k = 0; k < 4; ++k) {
        int p = offC[k];
        if (p < NPIX) {
            #pragma unroll
            for (int g = 0; g < 4; ++g) {
                float2 f = unpack2(acc[k][g]);
                dst[(o0 + 2 * g)     * NPIX + p] = f.x;
                dst[(o0 + 2 * g + 1) * NPIX + p] = f.y;
            }
        }
    }
}

// ------------------------------ main kernel ---------------------------------
__global__ void __launch_bounds__(NTHR, 1)
mix9s_kernel(const float* __restrict__ x,
             const float* __restrict__ dconv0_b,
             const float* __restrict__ res_dconv_b,
             const float* __restrict__ res_pw_b,
             const float* __restrict__ c0_b1,
             const float* __restrict__ c0_b2,
             const float* __restrict__ final_b,
             float* __restrict__ out)
{
    extern __shared__ float sm[];
    float* hA = sm;
    float* hB = sm + CM * STR;

    const int tid  = threadIdx.x;
    const int lane = tid & 31;
    const int wy   = tid >> 5;
    const int ph   = wy & 1;        // pixel half: 0 -> px 0..127, 1 -> 128..224
    const int cg   = wy >> 1;       // channel group (16 channels)
    const int d    = blockIdx.x & 3;
    const int b    = blockIdx.x >> 2;

    // per-direction tap offsets (fix_direction_order=True)
    int di0, dj0, di2, dj2;
    switch (d) {
        case 0:  di0 =  0; dj0 = -1; di2 =  0; dj2 =  1; break;
        case 1:  di0 = -1; dj0 =  0; di2 =  1; dj2 =  0; break;
        case 2:  di0 =  1; dj0 = -1; di2 = -1; dj2 =  1; break;
        default: di0 = -1; dj0 = -1; di2 =  1; dj2 =  1; break;
    }

    int offC[4], off0[4], off2[4];
    #pragma unroll
    for (int k = 0; k < 4; ++k) {
        int p  = 128 * ph + 32 * k + lane;
        int pc = (p < NPIX) ? p : NPIX;
        offC[k] = pc;
        int i = pc / 15, j = pc - i * 15;
        int i0 = i + di0, j0 = j + dj0, i2 = i + di2, j2 = j + dj2;
        int e0 = ((unsigned)i0 < 15u && (unsigned)j0 < 15u) ? i0 * 15 + j0 : NPIX;
        int e2 = ((unsigned)i2 < 15u && (unsigned)j2 < 15u) ? i2 * 15 + j2 : NPIX;
        if (pc == NPIX) { e0 = NPIX; e2 = NPIX; }
        off0[k] = e0; off2[k] = e2;
    }

    // stage x into hB channels 0/1
    for (int i = tid; i < 2 * STR; i += NTHR) {
        int c = i / STR, p = i - c * STR;
        hB[c * STR + p] = (p < NPIX) ? x[(b * 2 + c) * NPIX + p] : 0.0f;
    }
    // zero-sentinel slot 225 in every channel row of both buffers
    if (tid < 2 * CM) {
        int buf = tid >> 7, c = tid & 127;
        sm[buf * CM * STR + c * STR + NPIX] = 0.0f;
    }
    __syncthreads();

    const int o0 = cg * 16;

    conv_phase<2, true, false>(hB, hA, g_w0, dconv0_b, o0, offC, off0, off2);
    __syncthreads();

    #pragma unroll 1
    for (int l = 0; l < 4; ++l) {
        conv_phase<CM, true, false>(hA, hB, g_dw[l], res_dconv_b + l * CM,
                                    o0, offC, off0, off2);
        __syncthreads();
        conv_phase<CM, false, true>(hB, hA, g_pw[l], res_pw_b + l * CM,
                                    o0, offC, offC, offC);
        __syncthreads();
    }

    conv_phase<CM, false, false>(hA, hB, g_c01, c0_b1, o0, offC, offC, offC);
    __syncthreads();
    conv_phase<CM, false, true >(hB, hA, g_c02, c0_b2, o0, offC, offC, offC);
    __syncthreads();

    final_phase(hA, out + (size_t)blockIdx.x * CO * NPIX, g_fin, final_b,
                cg * 8, offC);
}

// ------------------------------ launch --------------------------------------
extern "C" void kernel_launch(void* const* d_in, const int* in_sizes, int n_in,
                              void* d_out, int out_size)
{
    const float* x           = (const float*)d_in[0];
    const float* dconv0_w    = (const float*)d_in[1];
    const float* dconv0_b    = (const float*)d_in[2];
    const float* res_dconv_w = (const float*)d_in[3];
    const float* res_dconv_b = (const float*)d_in[4];
    const float* res_pw_w    = (const float*)d_in[5];
    const float* res_pw_b    = (const float*)d_in[6];
    const float* c0_w1       = (const float*)d_in[7];
    const float* c0_b1       = (const float*)d_in[8];
    const float* c0_w2       = (const float*)d_in[9];
    const float* c0_b2       = (const float*)d_in[10];
    const float* final_w     = (const float*)d_in[11];
    const float* final_b     = (const float*)d_in[12];
    float* out = (float*)d_out;

    prep_kernel<<<192, 256>>>(dconv0_w, res_dconv_w, res_pw_w, c0_w1, c0_w2, final_w);

    cudaFuncSetAttribute(mix9s_kernel,
                         cudaFuncAttributeMaxDynamicSharedMemorySize, SMEM_BYTES);
    mix9s_kernel<<<1024, NTHR, SMEM_BYTES>>>(x, dconv0_b, res_dconv_b, res_pw_b,
                                             c0_b1, c0_b2, final_b, out);
}

// round 5
// speedup vs baseline: 1.0020x; 1.0020x over previous
#include <cuda_runtime.h>

// ============================================================================
// Fully-fused Mix9sNet: one CTA per (direction, batch) pair.
// Whole [128 x 225] activation plane resident in SMEM (double buffered).
// fp32 math via packed fma.rn.f32x2. Thread tile: 4 pixels x 16 channels
// (8 FMA2 per activation LDS).
// ============================================================================

typedef unsigned long long ULL;

#define CM    128
#define CO    64
#define NPIX  225
#define STR   226           // channel stride in smem; slot 225 is a zero sentinel
#define NTHR  512
#define SMEM_BYTES (2 * CM * STR * 4)   // 231424 bytes

// -------- pre-transposed weight scratch ([tap][c][o] / [c][o] layouts) ------
__device__ __align__(16) float g_w0 [3 * 2 * 128];
__device__ __align__(16) float g_dw [4][3 * 128 * 128];
__device__ __align__(16) float g_pw [4][128 * 128];
__device__ __align__(16) float g_c01[128 * 128];
__device__ __align__(16) float g_c02[128 * 128];
__device__ __align__(16) float g_fin[128 * 64];

// ------------------------------ f32x2 helpers -------------------------------
__device__ __forceinline__ ULL pack2(float lo, float hi) {
    ULL r; asm("mov.b64 %0, {%1, %2};" : "=l"(r) : "f"(lo), "f"(hi)); return r;
}
__device__ __forceinline__ float2 unpack2(ULL v) {
    float2 f; asm("mov.b64 {%0, %1}, %2;" : "=f"(f.x), "=f"(f.y) : "l"(v)); return f;
}
__device__ __forceinline__ void fma2(ULL& d, ULL a, ULL b) {
    asm("fma.rn.f32x2 %0, %1, %2, %0;" : "+l"(d) : "l"(a), "l"(b));
}
__device__ __forceinline__ float silu_f(float x) {
    return __fdividef(x, 1.0f + __expf(-x));
}

// ------------------------------ weight prep ---------------------------------
__global__ void prep_kernel(const float* __restrict__ w0,
                            const float* __restrict__ dw,
                            const float* __restrict__ pw,
                            const float* __restrict__ w1,
                            const float* __restrict__ w2,
                            const float* __restrict__ wf)
{
    int t  = blockIdx.x * blockDim.x + threadIdx.x;
    int nt = gridDim.x * blockDim.x;
    for (int i = t; i < 3 * 2 * 128; i += nt) {
        int tap = i / 256, c = (i >> 7) & 1, o = i & 127;
        g_w0[i] = w0[(o * 2 + c) * 3 + tap];
    }
    for (int i = t; i < 4 * 3 * 128 * 128; i += nt) {
        int l = i / (3 * 128 * 128);
        int r = i % (3 * 128 * 128);
        int tap = r / (128 * 128);
        int c = (r >> 7) & 127;
        int o = r & 127;
        g_dw[l][r] = dw[(((l * 128 + o) * 128 + c) * 3) + tap];
    }
    for (int i = t; i < 4 * 128 * 128; i += nt) {
        int l = i / 16384, r = i % 16384;
        int c = r >> 7, o = r & 127;
        g_pw[l][r] = pw[(l * 128 + o) * 128 + c];
    }
    for (int i = t; i < 128 * 128; i += nt) {
        int c = i >> 7, o = i & 127;
        g_c01[i] = w1[o * 128 + c];
        g_c02[i] = w2[o * 128 + c];
    }
    for (int i = t; i < 128 * 64; i += nt) {
        int c = i / 64, o = i % 64;
        g_fin[i] = wf[o * 128 + c];
    }
}

// ------------------------------ conv phases ---------------------------------
// Thread tile: 4 pixels (offC[0..3]) x 16 output channels (o0..o0+15).
// TAPS: 3-tap directional conv; RES: dst += silu(conv), else dst = silu(conv).
template<int CIN, bool TAPS, bool RES>
__device__ __forceinline__ void conv_phase(
    const float* __restrict__ src, float* __restrict__ dst,
    const float* __restrict__ Wt, const float* __restrict__ bias,
    int o0, const int* __restrict__ offC,
    const int* __restrict__ off0, const int* __restrict__ off2)
{
    ULL acc[4][8];
    {
        const ulonglong2* bv = reinterpret_cast<const ulonglong2*>(bias + o0);
        ulonglong2 t0 = bv[0], t1 = bv[1], t2 = bv[2], t3 = bv[3];
        ULL b[8] = {t0.x, t0.y, t1.x, t1.y, t2.x, t2.y, t3.x, t3.y};
        #pragma unroll
        for (int k = 0; k < 4; ++k)
            #pragma unroll
            for (int g = 0; g < 8; ++g) acc[k][g] = b[g];
    }

    #pragma unroll 2
    for (int c = 0; c < CIN; ++c) {
        const float* Sc = src + c * STR;
        {   // center tap
            const ulonglong2* wv = reinterpret_cast<const ulonglong2*>(
                Wt + ((TAPS ? CIN : 0) + c) * 128 + o0);
            ulonglong2 a = wv[0], b2 = wv[1], c2 = wv[2], d2 = wv[3];
            ULL w[8] = {a.x, a.y, b2.x, b2.y, c2.x, c2.y, d2.x, d2.y};
            #pragma unroll
            for (int k = 0; k < 4; ++k) {
                float v = Sc[offC[k]];
                ULL dv = pack2(v, v);
                #pragma unroll
                for (int g = 0; g < 8; ++g) fma2(acc[k][g], dv, w[g]);
            }
        }
        if (TAPS) {
            {   // tap 0
                const ulonglong2* wv = reinterpret_cast<const ulonglong2*>(
                    Wt + c * 128 + o0);
                ulonglong2 a = wv[0], b2 = wv[1], c2 = wv[2], d2 = wv[3];
                ULL w[8] = {a.x, a.y, b2.x, b2.y, c2.x, c2.y, d2.x, d2.y};
                #pragma unroll
                for (int k = 0; k < 4; ++k) {
                    float v = Sc[off0[k]];
                    ULL dv = pack2(v, v);
                    #pragma unroll
                    for (int g = 0; g < 8; ++g) fma2(acc[k][g], dv, w[g]);
                }
            }
            {   // tap 2
                const ulonglong2* wv = reinterpret_cast<const ulonglong2*>(
                    Wt + (2 * CIN + c) * 128 + o0);
                ulonglong2 a = wv[0], b2 = wv[1], c2 = wv[2], d2 = wv[3];
                ULL w[8] = {a.x, a.y, b2.x, b2.y, c2.x, c2.y, d2.x, d2.y};
                #pragma unroll
                for (int k = 0; k < 4; ++k) {
                    float v = Sc[off2[k]];
                    ULL dv = pack2(v, v);
                    #pragma unroll
                    for (int g = 0; g < 8; ++g) fma2(acc[k][g], dv, w[g]);
                }
            }
        }
    }

    #pragma unroll
    for (int k = 0; k < 4; ++k) {
        int p = offC[k];
        if (p < NPIX) {
            #pragma unroll
            for (int g = 0; g < 8; ++g) {
                float2 f = unpack2(acc[k][g]);
                float lo = silu_f(f.x), hi = silu_f(f.y);
                float* dp = dst + (o0 + 2 * g) * STR + p;
                if (RES) { dp[0] += lo; dp[STR] += hi; }
                else     { dp[0]  = lo; dp[STR]  = hi; }
            }
        }
    }
}

// final 1x1 conv (no activation): 4 px x 8 channels per thread, write global.
__device__ __forceinline__ void final_phase(
    const float* __restrict__ src, float* __restrict__ dst,
    const float* __restrict__ Wt, const float* __restrict__ bias,
    int o0, const int* __restrict__ offC)
{
    ULL acc[4][4];
    {
        const ulonglong2* bv = reinterpret_cast<const ulonglong2*>(bias + o0);
        ulonglong2 t0 = bv[0], t1 = bv[1];
        ULL b[4] = {t0.x, t0.y, t1.x, t1.y};
        #pragma unroll
        for (int k = 0; k < 4; ++k)
            #pragma unroll
            for (int g = 0; g < 4; ++g) acc[k][g] = b[g];
    }
    #pragma unroll 4
    for (int c = 0; c < CM; ++c) {
        const float* Sc = src + c * STR;
        const ulonglong2* wv = reinterpret_cast<const ulonglong2*>(Wt + c * CO + o0);
        ulonglong2 a = wv[0], b2 = wv[1];
        ULL w[4] = {a.x, a.y, b2.x, b2.y};
        #pragma unroll
        for (int k = 0; k < 4; ++k) {
            float v = Sc[offC[k]];
            ULL dv = pack2(v, v);
            #pragma unroll
            for (int g = 0; g < 4; ++g) fma2(acc[k][g], dv, w[g]);
        }
    }
    #pragma unroll
    for (int k = 0; k < 4; ++k) {
        int p = offC[k];
        if (p < NPIX) {
            #pragma unroll
            for (int g = 0; g < 4; ++g) {
                float2 f = unpack2(acc[k][g]);
                dst[(o0 + 2 * g)     * NPIX + p] = f.x;
                dst[(o0 + 2 * g + 1) * NPIX + p] = f.y;
            }
        }
    }
}

// ------------------------------ main kernel ---------------------------------
__global__ void __launch_bounds__(NTHR, 1)
mix9s_kernel(const float* __restrict__ x,
             const float* __restrict__ dconv0_b,
             const float* __restrict__ res_dconv_b,
             const float* __restrict__ res_pw_b,
             const float* __restrict__ c0_b1,
             const float* __restrict__ c0_b2,
             const float* __restrict__ final_b,
             float* __restrict__ out)
{
    extern __shared__ float sm[];
    float* hA = sm;
    float* hB = sm + CM * STR;

    const int tid  = threadIdx.x;
    const int lane = tid & 31;
    const int wy   = tid >> 5;
    const int ph   = wy & 1;        // pixel half: 0 -> px 0..127, 1 -> 128..224
    const int cg   = wy >> 1;       // channel group (16 channels)
    const int d    = blockIdx.x & 3;
    const int b    = blockIdx.x >> 2;

    // per-direction tap offsets (fix_direction_order=True)
    int di0, dj0, di2, dj2;
    switch (d) {
        case 0:  di0 =  0; dj0 = -1; di2 =  0; dj2 =  1; break;
        case 1:  di0 = -1; dj0 =  0; di2 =  1; dj2 =  0; break;
        case 2:  di0 =  1; dj0 = -1; di2 = -1; dj2 =  1; break;
        default: di0 = -1; dj0 = -1; di2 =  1; dj2 =  1; break;
    }

    int offC[4], off0[4], off2[4];
    #pragma unroll
    for (int k = 0; k < 4; ++k) {
        int p  = 128 * ph + 32 * k + lane;
        int pc = (p < NPIX) ? p : NPIX;
        offC[k] = pc;
        int i = pc / 15, j = pc - i * 15;
        int i0 = i + di0, j0 = j + dj0, i2 = i + di2, j2 = j + dj2;
        int e0 = ((unsigned)i0 < 15u && (unsigned)j0 < 15u) ? i0 * 15 + j0 : NPIX;
        int e2 = ((unsigned)i2 < 15u && (unsigned)j2 < 15u) ? i2 * 15 + j2 : NPIX;
        if (pc == NPIX) { e0 = NPIX; e2 = NPIX; }
        off0[k] = e0; off2[k] = e2;
    }

    // stage x into hB channels 0/1
    for (int i = tid; i < 2 * STR; i += NTHR) {
        int c = i / STR, p = i - c * STR;
        hB[c * STR + p] = (p < NPIX) ? x[(b * 2 + c) * NPIX + p] : 0.0f;
    }
    // zero-sentinel slot 225 in every channel row of both buffers
    if (tid < 2 * CM) {
        int buf = tid >> 7, c = tid & 127;
        sm[buf * CM * STR + c * STR + NPIX] = 0.0f;
    }
    __syncthreads();

    const int o0 = cg * 16;

    conv_phase<2, true, false>(hB, hA, g_w0, dconv0_b, o0, offC, off0, off2);
    __syncthreads();

    #pragma unroll 1
    for (int l = 0; l < 4; ++l) {
        conv_phase<CM, true, false>(hA, hB, g_dw[l], res_dconv_b + l * CM,
                                    o0, offC, off0, off2);
        __syncthreads();
        conv_phase<CM, false, true>(hB, hA, g_pw[l], res_pw_b + l * CM,
                                    o0, offC, offC, offC);
        __syncthreads();
    }

    conv_phase<CM, false, false>(hA, hB, g_c01, c0_b1, o0, offC, offC, offC);
    __syncthreads();
    conv_phase<CM, false, true >(hB, hA, g_c02, c0_b2, o0, offC, offC, offC);
    __syncthreads();

    final_phase(hA, out + (size_t)blockIdx.x * CO * NPIX, g_fin, final_b,
                cg * 8, offC);
}

// ------------------------------ launch --------------------------------------
extern "C" void kernel_launch(void* const* d_in, const int* in_sizes, int n_in,
                              void* d_out, int out_size)
{
    const float* x           = (const float*)d_in[0];
    const float* dconv0_w    = (const float*)d_in[1];
    const float* dconv0_b    = (const float*)d_in[2];
    const float* res_dconv_w = (const float*)d_in[3];
    const float* res_dconv_b = (const float*)d_in[4];
    const float* res_pw_w    = (const float*)d_in[5];
    const float* res_pw_b    = (const float*)d_in[6];
    const float* c0_w1       = (const float*)d_in[7];
    const float* c0_b1       = (const float*)d_in[8];
    const float* c0_w2       = (const float*)d_in[9];
    const float* c0_b2       = (const float*)d_in[10];
    const float* final_w     = (const float*)d_in[11];
    const float* final_b     = (const float*)d_in[12];
    float* out = (float*)d_out;

    prep_kernel<<<192, 256>>>(dconv0_w, res_dconv_w, res_pw_w, c0_w1, c0_w2, final_w);

    cudaFuncSetAttribute(mix9s_kernel,
                         cudaFuncAttributeMaxDynamicSharedMemorySize, SMEM_BYTES);
    mix9s_kernel<<<1024, NTHR, SMEM_BYTES>>>(x, dconv0_b, res_dconv_b, res_pw_b,
                                             c0_b1, c0_b2, final_b, out);
}